// round 1
// baseline (speedup 1.0000x reference)
#include <cuda_runtime.h>
#include <cuda_bf16.h>
#include <math.h>

// Problem constants (match reference_code)
#define HH 256
#define WW 336
#define HWPIX (HH * WW)            // 86016
#define BB 8
#define NEV 262144
#define FLOW_SCALING 336.0f
#define REG_WEIGHT 0.001f

// Accumulator layout: [b][tref][p][pix][2]  (2 = {iwe, iwe_ts}, adjacent for sector locality)
// Size: 8 * 2 * 2 * 86016 * 2 = 5,505,024 floats (~21 MB) -> L2 resident.
__device__ float g_acc[BB * 2 * 2 * HWPIX * 2];
__device__ double g_loss;

// ---------------------------------------------------------------------------
// Scatter: one thread per event. 2 trefs x 4 corners x 2 values = 16 atomics.
// ---------------------------------------------------------------------------
__global__ void __launch_bounds__(256) scatter_kernel(
    const float* __restrict__ flow,       // [B,2,H,W]
    const float* __restrict__ event_list) // [B,N,4] = {t, y, x, pol(+-1)}
{
    int tid = blockIdx.x * blockDim.x + threadIdx.x;
    if (tid >= BB * NEV) return;
    int b = tid / NEV;

    const float4 e = reinterpret_cast<const float4*>(event_list)[tid];
    const float ts = e.x;
    const float yy = e.y;
    const float xx = e.z;
    const int   p  = (e.w > 0.0f) ? 0 : 1;   // pol_mask: col0 = (pol==1), col1 = (pol==0)

    const int iy  = (int)yy;
    const int ix  = (int)xx;
    const int pix = iy * WW + ix;

    const float* fb = flow + (size_t)b * 2 * HWPIX;
    const float fx = fb[pix];           // channel 0 = x-flow
    const float fy = fb[HWPIX + pix];   // channel 1 = y-flow

#pragma unroll
    for (int tref = 0; tref < 2; ++tref) {
        const float dt = (float)tref - ts;
        const float wy = yy + dt * fy * FLOW_SCALING;
        const float wx = xx + dt * fx * FLOW_SCALING;
        const float tg = tref ? ts : (1.0f - ts);

        const float tyf = floorf(wy);
        const float lxf = floorf(wx);
        const int ty = (int)tyf;
        const int lx = (int)lxf;
        const float fry = wy - tyf;     // in [0,1)
        const float frx = wx - lxf;

        const float wyv[2] = {1.0f - fry, fry};
        const float wxv[2] = {1.0f - frx, frx};

        float* acc = g_acc + ((((size_t)b * 2 + tref) * 2 + p) * HWPIX) * 2;

#pragma unroll
        for (int cy = 0; cy < 2; ++cy) {
            const int y = ty + cy;
            if ((unsigned)y >= (unsigned)HH) continue;
#pragma unroll
            for (int cx = 0; cx < 2; ++cx) {
                const int x = lx + cx;
                if ((unsigned)x >= (unsigned)WW) continue;
                const float w = wyv[cy] * wxv[cx];
                if (w != 0.0f) {
                    float* a = acc + ((size_t)(y * WW + x)) * 2;
                    atomicAdd(a,     w);
                    atomicAdd(a + 1, w * tg);
                }
            }
        }
    }
}

// ---------------------------------------------------------------------------
// Block reduction helper (f32 partials -> double atomic)
// ---------------------------------------------------------------------------
__device__ __forceinline__ void block_reduce_add(float v) {
    __shared__ float sdata[32];
    const int lane = threadIdx.x & 31;
    const int warp = threadIdx.x >> 5;
#pragma unroll
    for (int off = 16; off > 0; off >>= 1)
        v += __shfl_down_sync(0xffffffffu, v, off);
    if (lane == 0) sdata[warp] = v;
    __syncthreads();
    if (warp == 0) {
        const int nwarps = (blockDim.x + 31) >> 5;
        float s = (lane < nwarps) ? sdata[lane] : 0.0f;
#pragma unroll
        for (int off = 16; off > 0; off >>= 1)
            s += __shfl_down_sync(0xffffffffu, s, off);
        if (lane == 0) atomicAdd(&g_loss, (double)s);
    }
}

// ---------------------------------------------------------------------------
// Loss reduction over accumulators: sum( (iwe_ts / (iwe + 1e-9))^2 )
// ---------------------------------------------------------------------------
__global__ void __launch_bounds__(256) reduce_loss_kernel() {
    const int total = BB * 2 * 2 * HWPIX;
    float sum = 0.0f;
    for (int i = blockIdx.x * blockDim.x + threadIdx.x; i < total;
         i += gridDim.x * blockDim.x) {
        const float2 v = reinterpret_cast<const float2*>(g_acc)[i];
        const float r = v.y / (v.x + 1e-9f);
        sum += r * r;
    }
    block_reduce_add(sum);
}

// ---------------------------------------------------------------------------
// Smoothness (Charbonnier) reduction over flow; scaled by REG_WEIGHT.
// ---------------------------------------------------------------------------
__global__ void __launch_bounds__(256) smooth_kernel(const float* __restrict__ flow) {
    const int total = BB * 2 * HWPIX;
    float sum = 0.0f;
    for (int i = blockIdx.x * blockDim.x + threadIdx.x; i < total;
         i += gridDim.x * blockDim.x) {
        const int o = i % HWPIX;
        const int h = o / WW;
        const int w = o % WW;
        const float v = flow[i];
        if (h < HH - 1) {
            const float d = v - flow[i + WW];
            sum += sqrtf(d * d + 1e-6f);
        }
        if (w < WW - 1) {
            const float d = v - flow[i + 1];
            sum += sqrtf(d * d + 1e-6f);
        }
    }
    block_reduce_add(sum * REG_WEIGHT);
}

// ---------------------------------------------------------------------------
// Final: write scalar result
// ---------------------------------------------------------------------------
__global__ void finalize_kernel(float* out) {
    out[0] = (float)g_loss;
}

extern "C" void kernel_launch(void* const* d_in, const int* in_sizes, int n_in,
                              void* d_out, int out_size) {
    const float* flow       = (const float*)d_in[0];  // 8*2*256*336
    const float* event_list = (const float*)d_in[1];  // 8*262144*4
    // d_in[2] = pol_mask (unused; polarity derived from event_list[...,3])
    float* out = (float*)d_out;

    void* acc_ptr = nullptr;
    void* loss_ptr = nullptr;
    cudaGetSymbolAddress(&acc_ptr, g_acc);
    cudaGetSymbolAddress(&loss_ptr, g_loss);

    cudaMemsetAsync(acc_ptr, 0, sizeof(float) * (size_t)BB * 2 * 2 * HWPIX * 2, 0);
    cudaMemsetAsync(loss_ptr, 0, sizeof(double), 0);

    const int nev_total = BB * NEV;
    scatter_kernel<<<(nev_total + 255) / 256, 256>>>(flow, event_list);
    reduce_loss_kernel<<<2048, 256>>>();
    smooth_kernel<<<1024, 256>>>(flow);
    finalize_kernel<<<1, 1>>>(out);
}

// round 2
// speedup vs baseline: 1.7796x; 1.7796x over previous
#include <cuda_runtime.h>
#include <cuda_bf16.h>
#include <math.h>

// Problem constants (match reference_code)
#define HH 256
#define WW 336
#define HWPIX (HH * WW)            // 86016
#define BB 8
#define NEV 262144
#define FLOW_SCALING 336.0f
#define REG_WEIGHT 0.001f

#define ACC_FLOATS ((size_t)BB * 2 * 2 * HWPIX * 2)   // 5,505,024 floats (~21 MB)

// One buffer: [acc floats][pad][double loss]  -> single memset clears everything.
// Align tail so the double is 8B-aligned (ACC_FLOATS is even -> already aligned).
__device__ float  g_acc[ACC_FLOATS + 4];
#define G_LOSS_PTR (reinterpret_cast<double*>(&g_acc[ACC_FLOATS]))

// ---------------------------------------------------------------------------
// Scatter: one thread per event. 2 trefs x 4 corners x ONE v2 red each.
// ---------------------------------------------------------------------------
__global__ void __launch_bounds__(256) scatter_kernel(
    const float* __restrict__ flow,       // [B,2,H,W]
    const float* __restrict__ event_list) // [B,N,4] = {t, y, x, pol(+-1)}
{
    int tid = blockIdx.x * blockDim.x + threadIdx.x;
    if (tid >= BB * NEV) return;
    int b = tid / NEV;

    const float4 e = reinterpret_cast<const float4*>(event_list)[tid];
    const float ts = e.x;
    const float yy = e.y;
    const float xx = e.z;
    const int   p  = (e.w > 0.0f) ? 0 : 1;   // pol_mask: col0 = (pol==1), col1 = (pol==0)

    const int iy  = (int)yy;
    const int ix  = (int)xx;
    const int pix = iy * WW + ix;

    const float* fb = flow + (size_t)b * 2 * HWPIX;
    const float fx = fb[pix];           // channel 0 = x-flow
    const float fy = fb[HWPIX + pix];   // channel 1 = y-flow

#pragma unroll
    for (int tref = 0; tref < 2; ++tref) {
        const float dt = (float)tref - ts;
        const float wy = yy + dt * fy * FLOW_SCALING;
        const float wx = xx + dt * fx * FLOW_SCALING;
        const float tg = tref ? ts : (1.0f - ts);

        const float tyf = floorf(wy);
        const float lxf = floorf(wx);
        const int ty = (int)tyf;
        const int lx = (int)lxf;
        const float fry = wy - tyf;     // in [0,1)
        const float frx = wx - lxf;

        const float wyv[2] = {1.0f - fry, fry};
        const float wxv[2] = {1.0f - frx, frx};

        float* acc = g_acc + ((((size_t)b * 2 + tref) * 2 + p) * HWPIX) * 2;

#pragma unroll
        for (int cy = 0; cy < 2; ++cy) {
            const int y = ty + cy;
            if ((unsigned)y >= (unsigned)HH) continue;
#pragma unroll
            for (int cx = 0; cx < 2; ++cx) {
                const int x = lx + cx;
                if ((unsigned)x >= (unsigned)WW) continue;
                const float w = wyv[cy] * wxv[cx];
                if (w != 0.0f) {
                    float* a = acc + ((size_t)(y * WW + x)) * 2;
                    // One 8B vector reduction for {iwe, iwe_ts}
                    asm volatile("red.global.add.v2.f32 [%0], {%1, %2};"
                                 :: "l"(a), "f"(w), "f"(w * tg) : "memory");
                }
            }
        }
    }
}

// ---------------------------------------------------------------------------
// Block reduction helper (f32 partials -> double atomic)
// ---------------------------------------------------------------------------
__device__ __forceinline__ void block_reduce_add(float v) {
    __shared__ float sdata[32];
    const int lane = threadIdx.x & 31;
    const int warp = threadIdx.x >> 5;
#pragma unroll
    for (int off = 16; off > 0; off >>= 1)
        v += __shfl_down_sync(0xffffffffu, v, off);
    if (lane == 0) sdata[warp] = v;
    __syncthreads();
    if (warp == 0) {
        const int nwarps = (blockDim.x + 31) >> 5;
        float s = (lane < nwarps) ? sdata[lane] : 0.0f;
#pragma unroll
        for (int off = 16; off > 0; off >>= 1)
            s += __shfl_down_sync(0xffffffffu, s, off);
        if (lane == 0) atomicAdd(G_LOSS_PTR, (double)s);
    }
}

// ---------------------------------------------------------------------------
// Fused reduction: loss over accumulators + Charbonnier smoothness over flow.
// ---------------------------------------------------------------------------
__global__ void __launch_bounds__(256) fused_reduce_kernel(const float* __restrict__ flow) {
    float sum = 0.0f;

    // Part 1: sum( (iwe_ts / (iwe + 1e-9))^2 ) over all 32 accumulator planes
    const int total_acc = BB * 2 * 2 * HWPIX;
    for (int i = blockIdx.x * blockDim.x + threadIdx.x; i < total_acc;
         i += gridDim.x * blockDim.x) {
        const float2 v = reinterpret_cast<const float2*>(g_acc)[i];
        const float r = v.y / (v.x + 1e-9f);
        sum += r * r;
    }

    // Part 2: REG_WEIGHT * sum( sqrt(d^2 + 1e-6) ) over flow dx & dy
    float ssum = 0.0f;
    const int total_flow = BB * 2 * HWPIX;
    for (int i = blockIdx.x * blockDim.x + threadIdx.x; i < total_flow;
         i += gridDim.x * blockDim.x) {
        const int o = i % HWPIX;
        const int h = o / WW;
        const int w = o % WW;
        const float v = flow[i];
        if (h < HH - 1) {
            const float d = v - flow[i + WW];
            ssum += sqrtf(d * d + 1e-6f);
        }
        if (w < WW - 1) {
            const float d = v - flow[i + 1];
            ssum += sqrtf(d * d + 1e-6f);
        }
    }
    sum += ssum * REG_WEIGHT;

    block_reduce_add(sum);
}

// ---------------------------------------------------------------------------
// Final: write scalar result
// ---------------------------------------------------------------------------
__global__ void finalize_kernel(float* out) {
    out[0] = (float)(*G_LOSS_PTR);
}

extern "C" void kernel_launch(void* const* d_in, const int* in_sizes, int n_in,
                              void* d_out, int out_size) {
    const float* flow       = (const float*)d_in[0];  // 8*2*256*336
    const float* event_list = (const float*)d_in[1];  // 8*262144*4
    // d_in[2] = pol_mask (unused; polarity derived from event_list[...,3])
    float* out = (float*)d_out;

    void* acc_ptr = nullptr;
    cudaGetSymbolAddress(&acc_ptr, g_acc);

    // Single memset clears accumulators AND the packed loss scalar.
    cudaMemsetAsync(acc_ptr, 0, sizeof(float) * (ACC_FLOATS + 4), 0);

    const int nev_total = BB * NEV;
    scatter_kernel<<<(nev_total + 255) / 256, 256>>>(flow, event_list);
    fused_reduce_kernel<<<2048, 256>>>(flow);
    finalize_kernel<<<1, 1>>>(out);
}

// round 4
// speedup vs baseline: 2.1854x; 1.2280x over previous
#include <cuda_runtime.h>
#include <cuda_fp16.h>
#include <cuda_bf16.h>
#include <math.h>

// Problem constants (match reference_code)
#define HH 256
#define WW 336
#define HWPIX (HH * WW)            // 86016
#define BB 8
#define NEV 262144
#define FLOW_SCALING 336.0f
#define REG_WEIGHT 0.001f

// ---------------------------------------------------------------------------
// Accumulator: fp16 pairs, two pair-grouping copies for guaranteed 8B alignment.
//
// Each 8B entry = [cell_lo: (iwe, iwe_ts) f16x2][cell_hi: (iwe, iwe_ts) f16x2]
// covering two x-adjacent pixels.
//   copy0: pair k covers x = (2k, 2k+1)
//   copy1: pair k covers x = (2k-1, 2k)
// A bilinear corner pair (lx, lx+1) is ALWAYS one aligned entry in copy (lx&1),
// pair index (lx+1)>>1.
// Rows padded to [-1, 256] (258 rows) so clamped OOB addresses stay in-buffer
// (their weights are zero -> value no-ops).
// Layout: [plane(32)][copy(2)][row(258)][pair(170)]  entries of 8B.
// ---------------------------------------------------------------------------
#define NPLANES   32                       // b(8) x tref(2) x p(2)
#define ROWS_PAD  258
#define PAIRS_PAD 170
#define COPY_STRIDE ((size_t)ROWS_PAD * PAIRS_PAD)          // 43860
#define PLANE_STRIDE (2 * COPY_STRIDE)                      // 87720
#define NENT ((size_t)NPLANES * PLANE_STRIDE)               // 2,807,040 entries (8B) ~22.5MB

// Tail: [NENT] = double loss accumulator, [NENT+1] = done-counter. One memset clears all.
__device__ __align__(16) unsigned long long g_acc[NENT + 2];

#define G_LOSS_PTR (reinterpret_cast<double*>(&g_acc[NENT]))
#define G_CTR_PTR  (reinterpret_cast<unsigned int*>(&g_acc[NENT + 1]))

// One 8B vector reduction: adds {lo, hi} f16x2 values to an aligned entry.
__device__ __forceinline__ void red_pair(unsigned long long* entry, __half2 lo, __half2 hi) {
    unsigned int ulo = *reinterpret_cast<unsigned int*>(&lo);
    unsigned int uhi = *reinterpret_cast<unsigned int*>(&hi);
    asm volatile("red.global.add.noftz.v2.f16x2 [%0], {%1, %2};"
                 :: "l"(entry), "r"(ulo), "r"(uhi) : "memory");
}

// ---------------------------------------------------------------------------
// Scatter: one thread per event. 2 trefs x 2 corner-rows = at most 4 REDs.
// ---------------------------------------------------------------------------
__global__ void __launch_bounds__(256) scatter_kernel(
    const float* __restrict__ flow,       // [B,2,H,W]
    const float* __restrict__ event_list) // [B,N,4] = {t, y, x, pol(+-1)}
{
    int tid = blockIdx.x * blockDim.x + threadIdx.x;
    if (tid >= BB * NEV) return;
    int b = tid / NEV;

    const float4 e = reinterpret_cast<const float4*>(event_list)[tid];
    const float ts = e.x;
    const float yy = e.y;
    const float xx = e.z;
    const int   p  = (e.w > 0.0f) ? 0 : 1;   // pol_mask: col0=(pol==1), col1=(pol==0)

    const int pix = (int)yy * WW + (int)xx;
    const float* fb = flow + (size_t)b * 2 * HWPIX;
    const float fx = fb[pix];           // channel 0 = x-flow
    const float fy = fb[HWPIX + pix];   // channel 1 = y-flow

#pragma unroll
    for (int tref = 0; tref < 2; ++tref) {
        const float dt = (float)tref - ts;
        const float wy = yy + dt * fy * FLOW_SCALING;
        const float wx = xx + dt * fx * FLOW_SCALING;
        const float tg = tref ? ts : (1.0f - ts);

        const float tyf = floorf(wy);
        const float lxf = floorf(wx);
        const int ty = (int)tyf;
        const int lx = (int)lxf;
        const float fry = wy - tyf;     // in [0,1)
        const float frx = wx - lxf;

        // Validity from TRUE corner coords (weights zeroed if OOB)
        const float wy0 = ((unsigned)ty       < HH) ? (1.0f - fry) : 0.0f;
        const float wy1 = ((unsigned)(ty + 1) < HH) ? fry          : 0.0f;
        const float wxl = ((unsigned)lx       < WW) ? (1.0f - frx) : 0.0f;
        const float wxr = ((unsigned)(lx + 1) < WW) ? frx          : 0.0f;

        // Clamp for addressing only (clamped cases have zero weights)
        const int tyc = min(max(ty, -1), HH - 1);
        const int lxc = min(max(lx, -1), WW - 1);

        const int copy = lxc & 1;
        const int pair = (lxc + 1) >> 1;
        const int plane = ((b * 2 + tref) * 2 + p);

        unsigned long long* e0 = g_acc
            + (size_t)plane * PLANE_STRIDE
            + (size_t)copy * COPY_STRIDE
            + (size_t)(tyc + 1) * PAIRS_PAD
            + pair;

        // Row 0 (y = tyc)
        {
            const float wl = wy0 * wxl, wr = wy0 * wxr;
            if (wl != 0.0f || wr != 0.0f) {
                red_pair(e0, __floats2half2_rn(wl, wl * tg),
                             __floats2half2_rn(wr, wr * tg));
            }
        }
        // Row 1 (y = tyc + 1)
        {
            const float wl = wy1 * wxl, wr = wy1 * wxr;
            if (wl != 0.0f || wr != 0.0f) {
                red_pair(e0 + PAIRS_PAD, __floats2half2_rn(wl, wl * tg),
                                         __floats2half2_rn(wr, wr * tg));
            }
        }
    }
}

// ---------------------------------------------------------------------------
// Block reduction helper (f32 partials -> double atomic)
// ---------------------------------------------------------------------------
__device__ __forceinline__ void block_reduce_add(float v) {
    __shared__ float sdata[32];
    const int lane = threadIdx.x & 31;
    const int warp = threadIdx.x >> 5;
#pragma unroll
    for (int off = 16; off > 0; off >>= 1)
        v += __shfl_down_sync(0xffffffffu, v, off);
    if (lane == 0) sdata[warp] = v;
    __syncthreads();
    if (warp == 0) {
        const int nwarps = (blockDim.x + 31) >> 5;
        float s = (lane < nwarps) ? sdata[lane] : 0.0f;
#pragma unroll
        for (int off = 16; off > 0; off >>= 1)
            s += __shfl_down_sync(0xffffffffu, s, off);
        if (lane == 0) atomicAdd(G_LOSS_PTR, (double)s);
    }
}

// ---------------------------------------------------------------------------
// Fused: loss over accumulators + Charbonnier smoothness + last-block finalize.
// ---------------------------------------------------------------------------
__global__ void __launch_bounds__(256) fused_reduce_kernel(
    const float* __restrict__ flow, float* __restrict__ out)
{
    float sum = 0.0f;

    // Part 1: sum( (iwe_ts / (iwe + 1e-9))^2 ), summing the two copies per cell.
    const __half2* h2 = reinterpret_cast<const __half2*>(g_acc);
    const int total_cells = NPLANES * HWPIX;
    for (int i = blockIdx.x * blockDim.x + threadIdx.x; i < total_cells;
         i += gridDim.x * blockDim.x) {
        const int plane = i / HWPIX;
        const int o = i - plane * HWPIX;
        const int y = o / WW;
        const int x = o - y * WW;

        const size_t base = (size_t)plane * PLANE_STRIDE + (size_t)(y + 1) * PAIRS_PAD;
        const size_t e0 = base + (x >> 1);                          // copy0
        const size_t e1 = base + COPY_STRIDE + ((x + 1) >> 1);      // copy1
        const int lane0 = x & 1;

        const float2 a  = __half22float2(h2[2 * e0 + lane0]);
        const float2 b2 = __half22float2(h2[2 * e1 + (lane0 ^ 1)]);
        const float iwe    = a.x + b2.x;
        const float iwe_ts = a.y + b2.y;
        const float r = iwe_ts / (iwe + 1e-9f);
        sum += r * r;
    }

    // Part 2: REG_WEIGHT * sum( sqrt(d^2 + 1e-6) ) over flow dx & dy
    float ssum = 0.0f;
    const int total_flow = BB * 2 * HWPIX;
    for (int i = blockIdx.x * blockDim.x + threadIdx.x; i < total_flow;
         i += gridDim.x * blockDim.x) {
        const int o = i % HWPIX;
        const int h = o / WW;
        const int w = o % WW;
        const float v = flow[i];
        if (h < HH - 1) {
            const float d = v - flow[i + WW];
            ssum += sqrtf(d * d + 1e-6f);
        }
        if (w < WW - 1) {
            const float d = v - flow[i + 1];
            ssum += sqrtf(d * d + 1e-6f);
        }
    }
    sum += ssum * REG_WEIGHT;

    block_reduce_add(sum);

    // Last block writes the final scalar (saves a finalize launch).
    __threadfence();
    if (threadIdx.x == 0) {
        unsigned int old = atomicAdd(G_CTR_PTR, 1u);
        if (old == gridDim.x - 1) {
            out[0] = (float)(*G_LOSS_PTR);
        }
    }
}

extern "C" void kernel_launch(void* const* d_in, const int* in_sizes, int n_in,
                              void* d_out, int out_size) {
    const float* flow       = (const float*)d_in[0];  // 8*2*256*336
    const float* event_list = (const float*)d_in[1];  // 8*262144*4
    // d_in[2] = pol_mask (unused; polarity derived from event_list[...,3])
    float* out = (float*)d_out;

    void* acc_ptr = nullptr;
    cudaGetSymbolAddress(&acc_ptr, g_acc);

    // Single memset clears accumulators, loss scalar, and done-counter.
    cudaMemsetAsync(acc_ptr, 0, sizeof(unsigned long long) * (NENT + 2), 0);

    const int nev_total = BB * NEV;
    scatter_kernel<<<(nev_total + 255) / 256, 256>>>(flow, event_list);
    fused_reduce_kernel<<<1024, 256>>>(flow, out);
}

// round 6
// speedup vs baseline: 2.8670x; 1.3119x over previous
#include <cuda_runtime.h>
#include <cuda_fp16.h>
#include <cuda_bf16.h>
#include <math.h>

// Problem constants (match reference_code)
#define HH 256
#define WW 336
#define HWPIX (HH * WW)            // 86016
#define BB 8
#define NEV 262144
#define FLOW_SCALING 336.0f
#define REG_WEIGHT 0.001f

// ---------------------------------------------------------------------------
// Accumulator: 16B "quad" entries, 4 parity-shifted copies.
//
// Quad entry (16B) = 4 cells, each an f16x2 {iwe, iwe_ts}:
//   lane0=(y0,x0) lane1=(y0,x0+1) lane2=(y0+1,x0) lane3=(y0+1,x0+1)
// Copy (cy,cx) tiles the padded image with quads starting at rows 2j-cy,
// cols 2k-cx. For a bilinear corner block (ty..ty+1, lx..lx+1), choosing
// cy=ty&1, cx=lx&1, j=(ty+cy)>>1, k=(lx+cx)>>1 makes the whole block ONE
// aligned quad -> one red.global.add.v4.f16x2 per (event, tref).
// Rows clamped to [-1,255], cols to [-1,335]; clamped slots hold zero weights.
// ---------------------------------------------------------------------------
#define NPLANES 32                 // b(8) x tref(2) x p(2)
#define RP 130                     // quad-rows per copy (j in [0,128], padded)
#define XP 170                     // quad-cols per copy (k in [0,168], padded)
#define COPY_ENT ((size_t)RP * XP)            // 22100 quads
#define PLANE_ENT (4 * COPY_ENT)              // 88400 quads (4 copies)
#define NQUAD ((size_t)NPLANES * PLANE_ENT)   // 2,828,800 quads (16B) ~45MB

// Backing store as ull pairs; tail holds double loss + done counter.
#define NULL_WORDS (NQUAD * 2)
__device__ __align__(16) unsigned long long g_acc[NULL_WORDS + 2];

#define G_LOSS_PTR (reinterpret_cast<double*>(&g_acc[NULL_WORDS]))
#define G_CTR_PTR  (reinterpret_cast<unsigned int*>(&g_acc[NULL_WORDS + 1]))

__device__ __forceinline__ void red_quad(void* entry,
                                         __half2 a, __half2 b, __half2 c, __half2 d) {
    unsigned int ua = *reinterpret_cast<unsigned int*>(&a);
    unsigned int ub = *reinterpret_cast<unsigned int*>(&b);
    unsigned int uc = *reinterpret_cast<unsigned int*>(&c);
    unsigned int ud = *reinterpret_cast<unsigned int*>(&d);
    asm volatile("red.global.add.noftz.v4.f16x2 [%0], {%1, %2, %3, %4};"
                 :: "l"(entry), "r"(ua), "r"(ub), "r"(uc), "r"(ud) : "memory");
}

// ---------------------------------------------------------------------------
// Scatter: one thread per event. 2 trefs x ONE 16B v4 red each.
// ---------------------------------------------------------------------------
__global__ void __launch_bounds__(256) scatter_kernel(
    const float* __restrict__ flow,       // [B,2,H,W]
    const float* __restrict__ event_list) // [B,N,4] = {t, y, x, pol(+-1)}
{
    int tid = blockIdx.x * blockDim.x + threadIdx.x;
    if (tid >= BB * NEV) return;
    int b = tid / NEV;

    const float4 e = reinterpret_cast<const float4*>(event_list)[tid];
    const float ts = e.x;
    const float yy = e.y;
    const float xx = e.z;
    const int   p  = (e.w > 0.0f) ? 0 : 1;   // pol_mask: col0=(pol==1), col1=(pol==0)

    const int pix = (int)yy * WW + (int)xx;
    const float* fb = flow + (size_t)b * 2 * HWPIX;
    const float fx = fb[pix];           // channel 0 = x-flow
    const float fy = fb[HWPIX + pix];   // channel 1 = y-flow

#pragma unroll
    for (int tref = 0; tref < 2; ++tref) {
        const float dt = (float)tref - ts;
        const float wy = yy + dt * fy * FLOW_SCALING;
        const float wx = xx + dt * fx * FLOW_SCALING;
        const float tg = tref ? ts : (1.0f - ts);

        const float tyf = floorf(wy);
        const float lxf = floorf(wx);
        const int ty = (int)tyf;
        const int lx = (int)lxf;
        const float fry = wy - tyf;     // in [0,1)
        const float frx = wx - lxf;

        // Validity from TRUE corner coords (weights zeroed if OOB)
        const float wy0 = ((unsigned)ty       < HH) ? (1.0f - fry) : 0.0f;
        const float wy1 = ((unsigned)(ty + 1) < HH) ? fry          : 0.0f;
        const float wxl = ((unsigned)lx       < WW) ? (1.0f - frx) : 0.0f;
        const float wxr = ((unsigned)(lx + 1) < WW) ? frx          : 0.0f;

        const float any = (wy0 + wy1) * (wxl + wxr);
        if (any == 0.0f) continue;

        // Clamp for addressing only (clamped slots get zero weights)
        const int tyc = min(max(ty, -1), HH - 1);
        const int lxc = min(max(lx, -1), WW - 1);

        const int cy = tyc & 1;
        const int cx = lxc & 1;
        const int j  = (tyc + cy) >> 1;
        const int k  = (lxc + cx) >> 1;
        const int plane = ((b * 2 + tref) * 2 + p);

        const size_t entry = (size_t)plane * PLANE_ENT
                           + (size_t)(cy * 2 + cx) * COPY_ENT
                           + (size_t)j * XP + k;

        const float w00 = wy0 * wxl, w01 = wy0 * wxr;
        const float w10 = wy1 * wxl, w11 = wy1 * wxr;

        red_quad(reinterpret_cast<char*>(g_acc) + entry * 16,
                 __floats2half2_rn(w00, w00 * tg),
                 __floats2half2_rn(w01, w01 * tg),
                 __floats2half2_rn(w10, w10 * tg),
                 __floats2half2_rn(w11, w11 * tg));
    }
}

// ---------------------------------------------------------------------------
// Block reduction helper (f32 partials -> double atomic)
// ---------------------------------------------------------------------------
__device__ __forceinline__ void block_reduce_add(float v) {
    __shared__ float sdata[32];
    const int lane = threadIdx.x & 31;
    const int warp = threadIdx.x >> 5;
#pragma unroll
    for (int off = 16; off > 0; off >>= 1)
        v += __shfl_down_sync(0xffffffffu, v, off);
    if (lane == 0) sdata[warp] = v;
    __syncthreads();
    if (warp == 0) {
        const int nwarps = (blockDim.x + 31) >> 5;
        float s = (lane < nwarps) ? sdata[lane] : 0.0f;
#pragma unroll
        for (int off = 16; off > 0; off >>= 1)
            s += __shfl_down_sync(0xffffffffu, s, off);
        if (lane == 0) atomicAdd(G_LOSS_PTR, (double)s);
    }
}

// Gather one cell's f16x2 slot from copy (cy,cx) of a plane (uint view).
__device__ __forceinline__ __half2 cell_slot(const unsigned int* plane_u,
                                             int cy, int cx, int y, int x) {
    const int r = y + cy, s = x + cx;
    const size_t uidx = (((size_t)(cy * 2 + cx) * COPY_ENT
                        + (size_t)(r >> 1) * XP + (s >> 1)) << 2)
                        + ((r & 1) << 1) + (s & 1);
    const unsigned int u = __ldg(plane_u + uidx);
    return *reinterpret_cast<const __half2*>(&u);
}

// ---------------------------------------------------------------------------
// Fused: loss over accumulators + Charbonnier smoothness + last-block finalize.
// ---------------------------------------------------------------------------
__global__ void __launch_bounds__(256) fused_reduce_kernel(
    const float* __restrict__ flow, float* __restrict__ out)
{
    float sum = 0.0f;

    // Part 1: sum( (iwe_ts / (iwe + 1e-9))^2 ), cell = sum of its slot in 4 copies.
    const unsigned int* accu = reinterpret_cast<const unsigned int*>(g_acc);
    const int total_cells = NPLANES * HWPIX;
    for (int i = blockIdx.x * blockDim.x + threadIdx.x; i < total_cells;
         i += gridDim.x * blockDim.x) {
        const int plane = i / HWPIX;
        const int o = i - plane * HWPIX;
        const int y = o / WW;
        const int x = o - y * WW;

        const unsigned int* pu = accu + (size_t)plane * PLANE_ENT * 4;
        __half2 h = __hadd2(__hadd2(cell_slot(pu, 0, 0, y, x),
                                    cell_slot(pu, 0, 1, y, x)),
                            __hadd2(cell_slot(pu, 1, 0, y, x),
                                    cell_slot(pu, 1, 1, y, x)));
        const float2 v = __half22float2(h);
        const float r = __fdividef(v.y, v.x + 1e-9f);
        sum += r * r;
    }

    // Part 2: REG_WEIGHT * sum( sqrt(d^2 + 1e-6) ) over flow dx & dy
    float ssum = 0.0f;
    const int total_flow = BB * 2 * HWPIX;
    for (int i = blockIdx.x * blockDim.x + threadIdx.x; i < total_flow;
         i += gridDim.x * blockDim.x) {
        const int o = i % HWPIX;
        const int h = o / WW;
        const int w = o % WW;
        const float v = flow[i];
        if (h < HH - 1) {
            const float d = v - flow[i + WW];
            ssum += sqrtf(d * d + 1e-6f);
        }
        if (w < WW - 1) {
            const float d = v - flow[i + 1];
            ssum += sqrtf(d * d + 1e-6f);
        }
    }
    sum += ssum * REG_WEIGHT;

    block_reduce_add(sum);

    // Last block writes the final scalar (saves a finalize launch).
    __threadfence();
    if (threadIdx.x == 0) {
        unsigned int old = atomicAdd(G_CTR_PTR, 1u);
        if (old == gridDim.x - 1) {
            out[0] = (float)(*G_LOSS_PTR);
        }
    }
}

extern "C" void kernel_launch(void* const* d_in, const int* in_sizes, int n_in,
                              void* d_out, int out_size) {
    const float* flow       = (const float*)d_in[0];  // 8*2*256*336
    const float* event_list = (const float*)d_in[1];  // 8*262144*4
    // d_in[2] = pol_mask (unused; polarity derived from event_list[...,3])
    float* out = (float*)d_out;

    void* acc_ptr = nullptr;
    cudaGetSymbolAddress(&acc_ptr, g_acc);

    // Single memset clears accumulators, loss scalar, and done-counter.
    cudaMemsetAsync(acc_ptr, 0, sizeof(unsigned long long) * (NULL_WORDS + 2), 0);

    const int nev_total = BB * NEV;
    scatter_kernel<<<(nev_total + 255) / 256, 256>>>(flow, event_list);
    fused_reduce_kernel<<<2048, 256>>>(flow, out);
}